// round 7
// baseline (speedup 1.0000x reference)
#include <cuda_runtime.h>
#include <cstdint>

#define Bdim 256
#define Udim 512
#define Ddim 512
#define N4U  2048

typedef unsigned long long ull;

// ---------------- scratch ----------------
__device__ float g_pre  [Bdim * N4U];         // gates pre-activations [B, 4U]
__device__ float g_hw   [Bdim * Udim];        // h_tm1 @ w
__device__ float g_red64[Bdim * 64 * Udim];   // partial hebb reductions (64 8-u chunks)
__device__ float g_g    [Bdim * Udim];        // eta[b,v]*itc[b,v]

// ---------------- packed f32x2 helpers ----------------
__device__ __forceinline__ ull pk2(float x, float y) {
    ull r; asm("mov.b64 %0, {%1, %2};" : "=l"(r) : "f"(x), "f"(y)); return r;
}
__device__ __forceinline__ ull fma2(ull a, ull b, ull c) {
    ull d; asm("fma.rn.f32x2 %0, %1, %2, %3;" : "=l"(d) : "l"(a), "l"(b), "l"(c)); return d;
}
__device__ __forceinline__ float2 upk(ull v) {
    float2 r; asm("mov.b64 {%0, %1}, %2;" : "=f"(r.x), "=f"(r.y) : "l"(v)); return r;
}

// =======================================================================
// Phase 1: one kernel
//   [0, 256)       : gates GEMM, 32x64 tiles
//   [256, 320)     : hw GEMM,    32x64 tiles
//   [320, 320+16384): hebb partial reduce — update-kernel clone shape
// =======================================================================

__device__ __forceinline__ void gemm32x64(
    const float* __restrict__ A1, const float* __restrict__ B1,
    const float* __restrict__ A2, const float* __restrict__ B2,
    const float* __restrict__ bias, float* __restrict__ C,
    int N, int m0, int n0, bool do_rec, bool add_bias, float* smem)
{
    const int K = 512;
    float (*As)[32] = (float(*)[32])smem;         // 16 x 32
    float (*Bs)[64] = (float(*)[64])(smem + 512); // 16 x 64

    int tid = threadIdx.x;
    int tx  = tid & 15;
    int ty  = tid >> 4;

    ull acc[2][2];
    acc[0][0] = acc[0][1] = acc[1][0] = acc[1][1] = 0ull;

    int npass = do_rec ? 2 : 1;
    for (int pass = 0; pass < npass; ++pass) {
        const float* A = pass ? A2 : A1;
        const float* B = pass ? B2 : B1;
        for (int k0 = 0; k0 < K; k0 += 16) {
            #pragma unroll
            for (int t = 0; t < 2; ++t) {
                int i = tid + t * 256;
                As[i & 15][i >> 4] = A[(m0 + (i >> 4)) * K + k0 + (i & 15)];
            }
            #pragma unroll
            for (int t = 0; t < 4; ++t) {
                int i = tid + t * 256;
                Bs[i >> 6][i & 63] = B[(k0 + (i >> 6)) * N + n0 + (i & 63)];
            }
            __syncthreads();
            #pragma unroll
            for (int kk = 0; kk < 16; ++kk) {
                float2 av = *(const float2*)&As[kk][ty * 2];
                ulonglong2 bv = *(const ulonglong2*)&Bs[kk][tx * 4];
                ull a0 = pk2(av.x, av.x);
                ull a1 = pk2(av.y, av.y);
                acc[0][0] = fma2(a0, bv.x, acc[0][0]);
                acc[0][1] = fma2(a0, bv.y, acc[0][1]);
                acc[1][0] = fma2(a1, bv.x, acc[1][0]);
                acc[1][1] = fma2(a1, bv.y, acc[1][1]);
            }
            __syncthreads();
        }
    }

    int n = n0 + tx * 4;
    float b0 = 0.f, b1 = 0.f, b2 = 0.f, b3 = 0.f;
    if (add_bias) { b0 = bias[n]; b1 = bias[n+1]; b2 = bias[n+2]; b3 = bias[n+3]; }
    #pragma unroll
    for (int r = 0; r < 2; ++r) {
        int m = m0 + ty * 2 + r;
        float2 lo = upk(acc[r][0]);
        float2 hi = upk(acc[r][1]);
        float4 o = make_float4(lo.x + b0, lo.y + b1, hi.x + b2, hi.y + b3);
        *(float4*)&C[m * N + n] = o;
    }
}

__global__ void __launch_bounds__(256) phase1_kernel(
    const float* __restrict__ x,     const float* __restrict__ kernel,
    const float* __restrict__ h_tm1, const float* __restrict__ rec,
    const float* __restrict__ bias,  const float* __restrict__ w,
    const float* __restrict__ hebb,
    float* __restrict__ pre, float* __restrict__ hw, float* __restrict__ red64)
{
    __shared__ __align__(16) float smem[1536];   // 6KB
    int bid = blockIdx.x;
    int tid = threadIdx.x;

    if (bid < 256) {
        int n0 = (bid & 31) * 64;
        int m0 = (bid >> 5) * 32;
        bool do_rec = !(n0 >= 2 * Udim && n0 < 3 * Udim);  // c-slice: no rec
        gemm32x64(x, kernel, h_tm1, rec, bias, pre, N4U, m0, n0, do_rec, true, smem);
    } else if (bid < 320) {
        int t  = bid - 256;
        int n0 = (t & 7) * 64;
        int m0 = (t >> 3) * 32;
        gemm32x64(h_tm1, w, nullptr, nullptr, nullptr, hw, Udim, m0, n0, false, false, smem);
    } else {
        // ---- hebb partial reduce: EXACT update-kernel shape ----
        // t covers f4 range [t*1024, t*1024+1024) = 8 u-rows x 128 v4.
        int t    = bid - 320;             // 0..16383
        int base = t * 1024 + tid;
        int v4   = tid & 127;

        // 4 uniform h loads (same addr across 128 threads -> L1 broadcast)
        int r0 = (base)           >> 7;   // = t*8 + (tid>>7) + 2k for k=0..3
        float hu0 = h_tm1[r0];
        float hu1 = h_tm1[r0 + 2];
        float hu2 = h_tm1[r0 + 4];
        float hu3 = h_tm1[r0 + 6];

        // 4 independent LDG.128, identical address stream to hebb_update
        float4 l0 = __ldcs(((const float4*)hebb) + base);
        float4 l1 = __ldcs(((const float4*)hebb) + base + 256);
        float4 l2 = __ldcs(((const float4*)hebb) + base + 512);
        float4 l3 = __ldcs(((const float4*)hebb) + base + 768);

        ull h0 = pk2(hu0, hu0), h1 = pk2(hu1, hu1);
        ull h2 = pk2(hu2, hu2), h3 = pk2(hu3, hu3);
        ulonglong2 v0 = *(ulonglong2*)&l0;
        ulonglong2 v1 = *(ulonglong2*)&l1;
        ulonglong2 v2 = *(ulonglong2*)&l2;
        ulonglong2 v3 = *(ulonglong2*)&l3;

        ull ax = fma2(h0, v0.x, 0ull);  ax = fma2(h1, v1.x, ax);
        ull bx = fma2(h2, v2.x, 0ull);  bx = fma2(h3, v3.x, bx);
        ull ay = fma2(h0, v0.y, 0ull);  ay = fma2(h1, v1.y, ay);
        ull by = fma2(h2, v2.y, 0ull);  by = fma2(h3, v3.y, by);

        float2 px = upk(ax), qx = upk(bx);
        float2 py = upk(ay), qy = upk(by);
        float4 acc = make_float4(px.x + qx.x, px.y + qx.y, py.x + qy.x, py.y + qy.y);

        // fold the two 128-thread halves (u-subsets {0,2,4,6} vs {1,3,5,7})
        float4* st = (float4*)smem;
        if (tid >= 128) st[v4] = acc;
        __syncthreads();
        if (tid < 128) {
            float4 o = st[v4];
            acc.x += o.x; acc.y += o.y; acc.z += o.z; acc.w += o.w;
            ((float4*)red64)[t * 128 + v4] = acc;   // red64[b][chunk][v]
        }
    }
}

// =======================================================================
// Phase 2: combine — gates, c, h, eta reduction, g   (256 blocks x 512)
// =======================================================================
__device__ __forceinline__ float hsig(float z) {
    return fminf(fmaxf(0.2f * z + 0.5f, 0.f), 1.f);
}

__global__ void __launch_bounds__(512) combine_kernel(
    const float* __restrict__ pre, const float* __restrict__ hw,
    const float* __restrict__ red64, const float* __restrict__ c_tm1,
    const float* __restrict__ alpha, const float* __restrict__ h2mod,
    const float* __restrict__ fanout,
    float* __restrict__ out, float* __restrict__ g)
{
    int b = blockIdx.x;
    int v = threadIdx.x;

    const float* r = red64 + (size_t)b * 64 * Udim + v;
    float s0 = 0.f, s1 = 0.f, s2 = 0.f, s3 = 0.f;
    #pragma unroll
    for (int j = 0; j < 64; j += 4) {
        s0 += r[(j + 0) * Udim];
        s1 += r[(j + 1) * Udim];
        s2 += r[(j + 2) * Udim];
        s3 += r[(j + 3) * Udim];
    }
    float red = (s0 + s1) + (s2 + s3);

    float xi = pre[b * N4U + v];
    float xf = pre[b * N4U + Udim + v];
    float xc = pre[b * N4U + 2 * Udim + v];
    float xo = pre[b * N4U + 3 * Udim + v];

    float gi = hsig(xi), gf = hsig(xf), go = hsig(xo);
    float itc = tanhf(xc + hw[b * Udim + v] + alpha[v] * red);
    float c = gf * c_tm1[b * Udim + v] + gi * itc;
    float h = go * tanhf(c);

    out[b * Udim + v] = h;
    out[Bdim * Udim + b * Udim + v] = c;

    float s = h * h2mod[v];
    #pragma unroll
    for (int o = 16; o > 0; o >>= 1) s += __shfl_down_sync(0xffffffffu, s, o);
    __shared__ float ws[16];
    __shared__ float eta_s;
    if ((v & 31) == 0) ws[v >> 5] = s;
    __syncthreads();
    if (v < 16) {
        float t = ws[v];
        #pragma unroll
        for (int o = 8; o > 0; o >>= 1) t += __shfl_down_sync(0xffffu, t, o);
        if (v == 0) eta_s = tanhf(t);
    }
    __syncthreads();
    g[b * Udim + v] = eta_s * fanout[v] * itc;
}

// =======================================================================
// Phase 3: hebb update — unchanged (near roofline)
// =======================================================================
__global__ void __launch_bounds__(256) hebb_update(
    const float* __restrict__ hebb, const float* __restrict__ h_tm1,
    const float* __restrict__ g, float* __restrict__ out)
{
    int base = blockIdx.x * 1024 + threadIdx.x;

    #pragma unroll
    for (int k = 0; k < 4; ++k) {
        int idx = base + k * 256;
        int row = idx >> 7;
        int v4  = idx & 127;
        int b   = idx >> 16;

        float hu = h_tm1[row];
        float4 hv = __ldcs(((const float4*)hebb) + idx);
        float4 gg = ((const float4*)(g + b * Udim))[v4];

        float4 r;
        r.x = fminf(fmaxf(hv.x + hu * gg.x, -2.f), 2.f);
        r.y = fminf(fmaxf(hv.y + hu * gg.y, -2.f), 2.f);
        r.z = fminf(fmaxf(hv.z + hu * gg.z, -2.f), 2.f);
        r.w = fminf(fmaxf(hv.w + hu * gg.w, -2.f), 2.f);
        __stcs(((float4*)out) + idx, r);
    }
}

// ---------------- launch ----------------
extern "C" void kernel_launch(void* const* d_in, const int* in_sizes, int n_in,
                              void* d_out, int out_size)
{
    const float* x      = (const float*)d_in[0];
    const float* h_tm1  = (const float*)d_in[1];
    const float* c_tm1  = (const float*)d_in[2];
    const float* hebb   = (const float*)d_in[3];
    const float* kernel = (const float*)d_in[4];
    const float* rec    = (const float*)d_in[5];
    const float* bias   = (const float*)d_in[6];
    const float* w      = (const float*)d_in[7];
    const float* alpha  = (const float*)d_in[8];
    const float* h2mod  = (const float*)d_in[9];
    const float* fanout = (const float*)d_in[10];
    float* out = (float*)d_out;

    float *pre, *hw, *red64, *gg;
    cudaGetSymbolAddress((void**)&pre,   g_pre);
    cudaGetSymbolAddress((void**)&hw,    g_hw);
    cudaGetSymbolAddress((void**)&red64, g_red64);
    cudaGetSymbolAddress((void**)&gg,    g_g);

    phase1_kernel<<<320 + 16384, 256>>>(x, kernel, h_tm1, rec, bias, w, hebb,
                                        pre, hw, red64);
    combine_kernel<<<Bdim, Udim>>>(pre, hw, red64, c_tm1, alpha, h2mod, fanout, out, gg);
    hebb_update<<<16384, 256>>>(hebb, h_tm1, gg, out + 2 * Bdim * Udim);
}